// round 12
// baseline (speedup 1.0000x reference)
#include <cuda_runtime.h>
#include <cstdint>

#define B_    4
#define C_    256
#define S_    1024
#define HEADS_ 8
#define D_    32
#define EPS_  1e-5f
#define KK2   0.2550635236562097f   // (1/sqrt(32)) * log2(e)

typedef unsigned long long u64;

// Scratch
__device__ float g_qkv[B_ * 3 * C_ * S_];       // [b][768][1024] (Q,K used)
__device__ float g_vt[B_ * HEADS_ * S_ * D_];   // [bh][s][d]
__device__ float g_att[B_ * C_ * S_];           // [b][256][1024]
__device__ float g_coefA[B_ * C_];
__device__ float g_coefB[B_ * C_];
__device__ float g_w4t[B_ * C_ * 3 * C_];       // [b][k][m] = w_qkv[m][k]*cA[b][k]
__device__ float g_bias4[B_ * 3 * C_];          // [b][m]
__device__ float g_wprojT[C_ * C_];             // [k][m]

// ---------------------------------------------------------------------------
// helpers
// ---------------------------------------------------------------------------
__device__ __forceinline__ u64 pk2(float lo, float hi) {
    u64 r; asm("mov.b64 %0, {%1, %2};" : "=l"(r) : "f"(lo), "f"(hi)); return r;
}
__device__ __forceinline__ void upk2(float& lo, float& hi, u64 v) {
    asm("mov.b64 {%0, %1}, %2;" : "=f"(lo), "=f"(hi) : "l"(v));
}
__device__ __forceinline__ void fma2(u64& d, u64 a, u64 b) {
    asm("fma.rn.f32x2 %0, %1, %2, %0;" : "+l"(d) : "l"(a), "l"(b));
}
__device__ __forceinline__ void mul2(u64& d, u64 a) {
    asm("mul.rn.f32x2 %0, %1, %0;" : "+l"(d) : "l"(a));
}
__device__ __forceinline__ float ex2(float x) {
    float r; asm("ex2.approx.ftz.f32 %0, %1;" : "=f"(r) : "f"(x)); return r;
}
__device__ __forceinline__ uint32_t smem_u32(const void* p) {
    uint32_t a;
    asm("{ .reg .u64 t; cvta.to.shared.u64 t, %1; cvt.u32.u64 %0, t; }"
        : "=r"(a) : "l"(p));
    return a;
}
__device__ __forceinline__ void cpa16(uint32_t dst, const void* src) {
    asm volatile("cp.async.ca.shared.global [%0], [%1], 16;"
                 :: "r"(dst), "l"(src) : "memory");
}
#define CPA_COMMIT() asm volatile("cp.async.commit_group;" ::: "memory")
#define CPA_WAIT0()  asm volatile("cp.async.wait_group 0;" ::: "memory")
#define CPA_WAIT1()  asm volatile("cp.async.wait_group 1;" ::: "memory")

// ---------------------------------------------------------------------------
// GroupNorm stats -> per-channel affine coefficients
// ---------------------------------------------------------------------------
__global__ __launch_bounds__(256) void gnstat_kernel(
    const float* __restrict__ x, const float* __restrict__ gamma,
    const float* __restrict__ beta) {
    int bg = blockIdx.x;
    int b = bg >> 5, g = bg & 31;
    const float4* x4 = (const float4*)(x + ((size_t)b * C_ + g * 8) * S_);
    int tid = threadIdx.x;
    float s0 = 0.f, s1 = 0.f;
    #pragma unroll
    for (int i = tid; i < 2048; i += 256) {
        float4 v = x4[i];
        s0 += v.x + v.y + v.z + v.w;
        s1 += v.x * v.x + v.y * v.y + v.z * v.z + v.w * v.w;
    }
    __shared__ float r0[256], r1[256];
    r0[tid] = s0; r1[tid] = s1;
    __syncthreads();
    for (int s = 128; s > 0; s >>= 1) {
        if (tid < s) { r0[tid] += r0[tid + s]; r1[tid] += r1[tid + s]; }
        __syncthreads();
    }
    if (tid < 8) {
        float m = r0[0] * (1.f / 8192.f);
        float var = r1[0] * (1.f / 8192.f) - m * m;
        float inv = rsqrtf(var + EPS_);
        int c = g * 8 + tid;
        float ga = gamma[c] * inv;
        g_coefA[b * C_ + c] = ga;
        g_coefB[b * C_ + c] = beta[c] - m * ga;
    }
}

// ---------------------------------------------------------------------------
// Merged prep kernel (one launch):
//   blocks [0, 768):    W4T[b][k][m] = w_qkv[m][k] * cA[b][k]
//   blocks [768, 1152): bias4[b][m]  = sum_k w_qkv[m][k] * cB[b][k]
//   blocks [1152,1216): wprojT[k][m] = w_proj[m][k]
// Staging tiles stride 36 (144 B rows, float4-aligned).
// ---------------------------------------------------------------------------
__global__ __launch_bounds__(256) void prep_all(
    const float* __restrict__ wq, const float* __restrict__ wp) {
    __shared__ float T[32][36];
    int bid = blockIdx.x;
    int tid = threadIdx.x;
    if (bid < 768) {
        int b = bid / 192, t = bid % 192;
        int kt = t / 24, mt = t % 24;
        int m0 = mt * 32, k0 = kt * 32;
        int r = tid >> 3, c4 = (tid & 7) * 4;
        *(float4*)&T[r][c4] = *(const float4*)&wq[(size_t)(m0 + r) * C_ + k0 + c4];
        __syncthreads();
        int kk = r, m4 = c4;
        float a = g_coefA[b * C_ + k0 + kk];
        float4 o = make_float4(T[m4][kk] * a, T[m4 + 1][kk] * a,
                               T[m4 + 2][kk] * a, T[m4 + 3][kk] * a);
        *(float4*)&g_w4t[((size_t)b * C_ + k0 + kk) * (3 * C_) + m0 + m4] = o;
    } else if (bid < 1152) {
        int t = bid - 768;
        int b = t / 96, mg = t % 96;
        int m = mg * 8 + (tid >> 5);
        int lane = tid & 31;
        const float* cB = g_coefB + b * C_;
        float s = 0.f;
        #pragma unroll
        for (int k = lane; k < C_; k += 32) s += wq[(size_t)m * C_ + k] * cB[k];
        #pragma unroll
        for (int msk = 16; msk > 0; msk >>= 1)
            s += __shfl_xor_sync(0xffffffffu, s, msk);
        if (lane == 0) g_bias4[b * 3 * C_ + m] = s;
    } else {
        int t = bid - 1152;
        int mt = t % 8, kt = t / 8;
        int m0 = mt * 32, k0 = kt * 32;
        int r = tid >> 3, c4 = (tid & 7) * 4;
        *(float4*)&T[r][c4] = *(const float4*)&wp[(size_t)(m0 + r) * C_ + k0 + c4];
        __syncthreads();
        int kk = r, m4 = c4;
        float4 o = make_float4(T[m4][kk], T[m4 + 1][kk], T[m4 + 2][kk], T[m4 + 3][kk]);
        *(float4*)&g_wprojT[(size_t)(k0 + kk) * C_ + m0 + m4] = o;
    }
}

// ---------------------------------------------------------------------------
// cp.async pipelined GEMM (k-major weights). Same as round-11 passing version.
// ---------------------------------------------------------------------------
template <bool QKV, int BM, int RM>
__global__ __launch_bounds__(256, 3) void gemm_cp(
    const float* __restrict__ WT, const float* __restrict__ X,
    float* __restrict__ Out, const float* __restrict__ bias,
    const float* __restrict__ resid, int M) {
    __shared__ __align__(16) float As[2][16][BM];
    __shared__ __align__(16) float Bs[2][16][64];
    const int NA = BM / 64;

    int tid = threadIdx.x;
    int b = blockIdx.z, m0 = blockIdx.y * BM, n0 = blockIdx.x * 64;
    const float* Wb = WT + (QKV ? (size_t)b * C_ * M : 0);
    const float* Xb = X + (size_t)b * C_ * S_;
    uint32_t aA[2] = { smem_u32(&As[0][0][0]), smem_u32(&As[1][0][0]) };
    uint32_t aB[2] = { smem_u32(&Bs[0][0][0]), smem_u32(&Bs[1][0][0]) };

#define LOADST(CH, ST) do {                                                   \
    int kb_ = (CH) * 16;                                                      \
    _Pragma("unroll")                                                         \
    for (int u_ = 0; u_ < NA; u_++) {                                         \
        int idx_ = tid + u_ * 256;                                            \
        int k_ = idx_ / (BM / 4), m4_ = (idx_ % (BM / 4)) * 4;                \
        cpa16(aA[ST] + (k_ * BM + m4_) * 4,                                   \
              Wb + (size_t)(kb_ + k_) * M + m0 + m4_);                        \
    }                                                                         \
    {                                                                         \
        int k_ = tid >> 4, n4_ = (tid & 15) * 4;                              \
        cpa16(aB[ST] + (k_ * 64 + n4_) * 4,                                   \
              Xb + (size_t)(kb_ + k_) * S_ + n0 + n4_);                       \
    }                                                                         \
} while (0)

    LOADST(0, 0); CPA_COMMIT();
    LOADST(1, 1); CPA_COMMIT();

    int rg = tid >> 4, cg = tid & 15;
    u64 acc[RM][2] = {};

    #pragma unroll
    for (int ch = 0; ch < 16; ch++) {
        int st = ch & 1;
        if (ch == 15) { CPA_WAIT0(); } else { CPA_WAIT1(); }
        __syncthreads();
        #pragma unroll
        for (int k = 0; k < 16; k++) {
            float4 bv = *(float4*)&Bs[st][k][cg * 4];
            u64 bp0 = pk2(bv.x, bv.y), bp1 = pk2(bv.z, bv.w);
            float a[RM];
            #pragma unroll
            for (int t = 0; t < RM / 4; t++) {
                float4 av = *(float4*)&As[st][k][rg * RM + t * 4];
                a[t * 4 + 0] = av.x; a[t * 4 + 1] = av.y;
                a[t * 4 + 2] = av.z; a[t * 4 + 3] = av.w;
            }
            #pragma unroll
            for (int i = 0; i < RM; i++) {
                u64 ab = pk2(a[i], a[i]);
                fma2(acc[i][0], ab, bp0);
                fma2(acc[i][1], ab, bp1);
            }
        }
        __syncthreads();
        if (ch + 2 < 16) { LOADST(ch + 2, st); CPA_COMMIT(); }
    }
#undef LOADST

    float o[RM][4];
    #pragma unroll
    for (int i = 0; i < RM; i++) {
        upk2(o[i][0], o[i][1], acc[i][0]);
        upk2(o[i][2], o[i][3], acc[i][1]);
    }

    if (QKV && m0 >= 512) {
        #pragma unroll
        for (int i = 0; i < RM; i++) {
            float bv = bias[b * M + m0 + rg * RM + i];
            #pragma unroll
            for (int u = 0; u < 4; u++) o[i][u] += bv;
        }
        int mb = m0 - 512 + rg * RM;
        int h = mb >> 5, db = mb & 31;
        float* vdst = g_vt + (size_t)(b * 8 + h) * 1024 * 32;
        #pragma unroll
        for (int u = 0; u < 4; u++) {
            int s = n0 + cg * 4 + u;
            *(float4*)&vdst[(size_t)s * 32 + db] =
                make_float4(o[0][u], o[1][u], o[2][u], o[3][u]);
            *(float4*)&vdst[(size_t)s * 32 + db + 4] =
                make_float4(o[4][u], o[5][u], o[6][u], o[7][u]);
        }
        return;
    }

    #pragma unroll
    for (int i = 0; i < RM; i++) {
        int m = m0 + rg * RM + i;
        float bv = bias[(QKV ? b * M : 0) + m];
        size_t off = ((size_t)b * M + m) * S_ + n0 + cg * 4;
        float4 v = make_float4(o[i][0] + bv, o[i][1] + bv,
                               o[i][2] + bv, o[i][3] + bv);
        if (!QKV) {
            float4 rr = *(const float4*)&resid[off];
            v.x += rr.x; v.y += rr.y; v.z += rr.z; v.w += rr.w;
        }
        *(float4*)&Out[off] = v;
    }
}

// ---------------------------------------------------------------------------
// Fused flash attention v4: BQ=64, 256 threads, occupancy 2 (smem 106.8 KB).
// QK: 4i x 8j microtile. PV: 4i x 8d, 4-way j-split, reduced via scratch.
// Strides: Qs 64, Ks 128, Vt 32, Ps 68, partial 36 (all float4-aligned).
// ---------------------------------------------------------------------------
#define FQ_QS   0
#define FQ_KS0  2048
#define FQ_KS1  6144
#define FQ_VT0  10240
#define FQ_VT1  14336
#define FQ_PS   18432
#define FQ_MX   27136
#define FQ_SL   27200
#define FQ_SC   27264
#define FQ_TOT  27328
#define RQ_STR  36
#define RQ_SZ   (64 * RQ_STR)     // 2304 floats per partial region (x3 fits Ps)

__global__ __launch_bounds__(256, 2) void flash_kernel() {
    extern __shared__ float sh[];
    float* Qs  = sh + FQ_QS;
    float* Ps  = sh + FQ_PS;
    float* smx = sh + FQ_MX;
    float* sl  = sh + FQ_SL;
    float* sc  = sh + FQ_SC;

    int tid = threadIdx.x;
    int bh = blockIdx.y, b = bh >> 3, h = bh & 7;
    int i0 = blockIdx.x * 64;
    const float* qb  = g_qkv + ((size_t)(b * 768 + h * 32)) * 1024;
    const float* kb  = g_qkv + ((size_t)(b * 768 + 256 + h * 32)) * 1024;
    const float* vtg = g_vt + (size_t)bh * 1024 * 32;

    uint32_t ksb[2] = { smem_u32(sh + FQ_KS0), smem_u32(sh + FQ_KS1) };
    uint32_t vtb[2] = { smem_u32(sh + FQ_VT0), smem_u32(sh + FQ_VT1) };

    // async-load tile 0 (K 32x128 stride 128; V 128x32 stride 32)
    #pragma unroll
    for (int t = 0; t < 4; t++) {
        int idx = tid + t * 256;
        int d = idx >> 5, c4 = (idx & 31) * 4;
        cpa16(ksb[0] + (d * 128 + c4) * 4, kb + (size_t)d * 1024 + c4);
        int j = idx >> 3, d4 = (idx & 7) * 4;
        cpa16(vtb[0] + (j * 32 + d4) * 4, vtg + (size_t)j * 32 + d4);
    }
    CPA_COMMIT();

    // Q tile [32 d][64 i], stride 64
    #pragma unroll
    for (int t = 0; t < 2; t++) {
        int idx = tid + t * 256;
        int d = idx >> 4, c4 = (idx & 15) * 4;
        *(float4*)&Qs[d * 64 + c4] = *(const float4*)(qb + (size_t)d * 1024 + i0 + c4);
    }
    if (tid < 64) { smx[tid] = -1e30f; sl[tid] = 0.f; }

    const int rg = tid >> 4, cg = tid & 15, ri0 = rg * 4;
    const int jgrp = tid >> 6, r6 = tid & 63;
    const int i8 = (r6 >> 2) * 4, d0 = (r6 & 3) * 8;

    u64 Oa[4][4] = {};   // 4 i-rows x 4 d-pairs

    for (int jt = 0; jt < 8; jt++) {
        float* Ks = sh + ((jt & 1) ? FQ_KS1 : FQ_KS0);
        float* Vt = sh + ((jt & 1) ? FQ_VT1 : FQ_VT0);
        CPA_WAIT0();
        __syncthreads();
        if (jt < 7) {
            int j1 = (jt + 1) * 128;
            int bn = (jt + 1) & 1;
            #pragma unroll
            for (int t = 0; t < 4; t++) {
                int idx = tid + t * 256;
                int d = idx >> 5, c4 = (idx & 31) * 4;
                cpa16(ksb[bn] + (d * 128 + c4) * 4, kb + (size_t)d * 1024 + j1 + c4);
                int j = idx >> 3, d4 = (idx & 7) * 4;
                cpa16(vtb[bn] + (j * 32 + d4) * 4, vtg + (size_t)(j1 + j) * 32 + d4);
            }
            CPA_COMMIT();
        }

        // --- QK^T: 4i x 8j ---
        u64 qk[2][8] = {};
        #pragma unroll
        for (int d = 0; d < 32; d++) {
            float4 q = *(float4*)&Qs[d * 64 + ri0];
            u64 q01 = pk2(q.x, q.y), q23 = pk2(q.z, q.w);
            #pragma unroll
            for (int jj = 0; jj < 8; jj++) {
                float kv = Ks[d * 128 + cg + 16 * jj];
                u64 kp = pk2(kv, kv);
                fma2(qk[0][jj], q01, kp);
                fma2(qk[1][jj], q23, kp);
            }
        }
        float s[4][8];
        #pragma unroll
        for (int jj = 0; jj < 8; jj++) {
            upk2(s[0][jj], s[1][jj], qk[0][jj]);
            upk2(s[2][jj], s[3][jj], qk[1][jj]);
        }

        // --- online softmax (4 rows/thread, reduce across 16 cg lanes) ---
        float mold[4], mnew[4], rsum[4];
        #pragma unroll
        for (int ii = 0; ii < 4; ii++) {
            float mx = s[ii][0];
            #pragma unroll
            for (int jj = 1; jj < 8; jj++) mx = fmaxf(mx, s[ii][jj]);
            #pragma unroll
            for (int msk = 1; msk < 16; msk <<= 1)
                mx = fmaxf(mx, __shfl_xor_sync(0xffffffffu, mx, msk));
            mold[ii] = smx[ri0 + ii];
            mnew[ii] = fmaxf(mold[ii], mx);
            float nk = -mnew[ii] * KK2;
            float r = 0.f;
            #pragma unroll
            for (int jj = 0; jj < 8; jj++) {
                float p = ex2(fmaf(s[ii][jj], KK2, nk));
                s[ii][jj] = p;
                r += p;
            }
            #pragma unroll
            for (int msk = 1; msk < 16; msk <<= 1)
                r += __shfl_xor_sync(0xffffffffu, r, msk);
            rsum[ii] = r;
        }
        if (cg == 0) {
            #pragma unroll
            for (int ii = 0; ii < 4; ii++) {
                float c = ex2((mold[ii] - mnew[ii]) * KK2);
                sc[ri0 + ii] = c;
                smx[ri0 + ii] = mnew[ii];
                sl[ri0 + ii] = sl[ri0 + ii] * c + rsum[ii];
            }
        }
        // store P j-major: Ps[col][i], stride 68
        #pragma unroll
        for (int jj = 0; jj < 8; jj++) {
            int col = cg + 16 * jj;
            *(float4*)&Ps[col * 68 + ri0] =
                make_float4(s[0][jj], s[1][jj], s[2][jj], s[3][jj]);
        }
        __syncthreads();

        // --- P @ V: 4i x 8d over this thread's 32-j quarter ---
        #pragma unroll
        for (int ii = 0; ii < 4; ii++) {
            float cc = sc[i8 + ii];
            u64 cb = pk2(cc, cc);
            mul2(Oa[ii][0], cb); mul2(Oa[ii][1], cb);
            mul2(Oa[ii][2], cb); mul2(Oa[ii][3], cb);
        }
        int jb = jgrp * 32;
        #pragma unroll 4
        for (int jo = 0; jo < 32; jo++) {
            int j = jb + jo;
            float4 p = *(float4*)&Ps[j * 68 + i8];
            float4 v0 = *(float4*)&Vt[j * 32 + d0];
            float4 v1 = *(float4*)&Vt[j * 32 + d0 + 4];
            u64 vp[4] = { pk2(v0.x, v0.y), pk2(v0.z, v0.w),
                          pk2(v1.x, v1.y), pk2(v1.z, v1.w) };
            float pv[4] = { p.x, p.y, p.z, p.w };
            #pragma unroll
            for (int ii = 0; ii < 4; ii++) {
                u64 pbx = pk2(pv[ii], pv[ii]);
                fma2(Oa[ii][0], pbx, vp[0]);
                fma2(Oa[ii][1], pbx, vp[1]);
                fma2(Oa[ii][2], pbx, vp[2]);
                fma2(Oa[ii][3], pbx, vp[3]);
            }
        }
    }
    __syncthreads();

    // 4-way partial reduce via Ps scratch (stride 36, 16B aligned)
    float o[4][8];
    #pragma unroll
    for (int ii = 0; ii < 4; ii++) {
        upk2(o[ii][0], o[ii][1], Oa[ii][0]);
        upk2(o[ii][2], o[ii][3], Oa[ii][1]);
        upk2(o[ii][4], o[ii][5], Oa[ii][2]);
        upk2(o[ii][6], o[ii][7], Oa[ii][3]);
    }
    if (jgrp > 0) {
        float* dst = Ps + (jgrp - 1) * RQ_SZ;
        #pragma unroll
        for (int ii = 0; ii < 4; ii++) {
            *(float4*)&dst[(i8 + ii) * RQ_STR + d0] =
                make_float4(o[ii][0], o[ii][1], o[ii][2], o[ii][3]);
            *(float4*)&dst[(i8 + ii) * RQ_STR + d0 + 4] =
                make_float4(o[ii][4], o[ii][5], o[ii][6], o[ii][7]);
        }
    }
    __syncthreads();
    if (jgrp == 0) {
        float* ob = g_att + ((size_t)(b * 256 + h * 32)) * 1024 + i0;
        #pragma unroll
        for (int ii = 0; ii < 4; ii++) {
            #pragma unroll
            for (int g = 0; g < 3; g++) {
                float4 pa = *(float4*)&Ps[g * RQ_SZ + (i8 + ii) * RQ_STR + d0];
                float4 pb2 = *(float4*)&Ps[g * RQ_SZ + (i8 + ii) * RQ_STR + d0 + 4];
                o[ii][0] += pa.x;  o[ii][1] += pa.y;
                o[ii][2] += pa.z;  o[ii][3] += pa.w;
                o[ii][4] += pb2.x; o[ii][5] += pb2.y;
                o[ii][6] += pb2.z; o[ii][7] += pb2.w;
            }
            float linv = 1.f / sl[i8 + ii];
            #pragma unroll
            for (int dd = 0; dd < 8; dd++) o[ii][dd] *= linv;
        }
        #pragma unroll
        for (int dd = 0; dd < 8; dd++) {
            *(float4*)&ob[(size_t)(d0 + dd) * 1024 + i8] =
                make_float4(o[0][dd], o[1][dd], o[2][dd], o[3][dd]);
        }
    }
}

// ---------------------------------------------------------------------------
extern "C" void kernel_launch(void* const* d_in, const int* in_sizes, int n_in,
                              void* d_out, int out_size) {
    const float* x      = (const float*)d_in[0];
    const float* gamma  = (const float*)d_in[1];
    const float* beta   = (const float*)d_in[2];
    const float* w_qkv  = (const float*)d_in[3];
    const float* w_proj = (const float*)d_in[4];
    const float* b_proj = (const float*)d_in[5];
    float* out = (float*)d_out;

    float* qkv;   cudaGetSymbolAddress((void**)&qkv, g_qkv);
    float* att;   cudaGetSymbolAddress((void**)&att, g_att);
    float* w4t;   cudaGetSymbolAddress((void**)&w4t, g_w4t);
    float* bias4; cudaGetSymbolAddress((void**)&bias4, g_bias4);
    float* wpT;   cudaGetSymbolAddress((void**)&wpT, g_wprojT);

    static int smem_set = 0;
    const int FLASH_SMEM = FQ_TOT * 4;   // 109312 B -> occupancy 2
    if (!smem_set) {
        cudaFuncSetAttribute(flash_kernel,
                             cudaFuncAttributeMaxDynamicSharedMemorySize,
                             FLASH_SMEM);
        smem_set = 1;
    }

    // 1. GroupNorm stats
    gnstat_kernel<<<B_ * 32, 256>>>(x, gamma, beta);

    // 2. Merged weight preps
    prep_all<<<1216, 256>>>(w_qkv, w_proj);

    // 3. QKV GEMM (V -> g_vt transposed)
    {
        dim3 grid(S_ / 64, (3 * C_) / 128, B_);
        gemm_cp<true, 128, 8><<<grid, 256>>>(w4t, x, qkv, bias4, nullptr, 3 * C_);
    }

    // 4. Fused flash attention (BQ=64, occupancy 2)
    {
        dim3 grid(S_ / 64, B_ * HEADS_);
        flash_kernel<<<grid, 256, FLASH_SMEM>>>();
    }

    // 5. Proj + bias + residual
    {
        dim3 grid(S_ / 64, C_ / 64, B_);
        gemm_cp<false, 64, 4><<<grid, 256>>>(wpT, att, out, b_proj, x, C_);
    }
}

// round 14
// speedup vs baseline: 1.1365x; 1.1365x over previous
#include <cuda_runtime.h>
#include <cstdint>

#define B_    4
#define C_    256
#define S_    1024
#define HEADS_ 8
#define D_    32
#define EPS_  1e-5f
#define KK2   0.2550635236562097f   // (1/sqrt(32)) * log2(e)

typedef unsigned long long u64;

// Scratch
__device__ float g_qkv[B_ * 3 * C_ * S_];       // [b][768][1024] (Q,K used)
__device__ float g_vt[B_ * HEADS_ * S_ * D_];   // [bh][s][d]
__device__ float g_att[B_ * C_ * S_];           // [b][256][1024]
__device__ float g_coefA[B_ * C_];
__device__ float g_coefB[B_ * C_];
__device__ float g_w4t[B_ * C_ * 3 * C_];       // [b][k][m] = w_qkv[m][k]*cA[b][k]
__device__ float g_bias4[B_ * 3 * C_];          // [b][m]
__device__ float g_wprojT[C_ * C_];             // [k][m]

// ---------------------------------------------------------------------------
// helpers
// ---------------------------------------------------------------------------
__device__ __forceinline__ u64 pk2(float lo, float hi) {
    u64 r; asm("mov.b64 %0, {%1, %2};" : "=l"(r) : "f"(lo), "f"(hi)); return r;
}
__device__ __forceinline__ void upk2(float& lo, float& hi, u64 v) {
    asm("mov.b64 {%0, %1}, %2;" : "=f"(lo), "=f"(hi) : "l"(v));
}
__device__ __forceinline__ void fma2(u64& d, u64 a, u64 b) {
    asm("fma.rn.f32x2 %0, %1, %2, %0;" : "+l"(d) : "l"(a), "l"(b));
}
__device__ __forceinline__ void mul2(u64& d, u64 a) {
    asm("mul.rn.f32x2 %0, %1, %0;" : "+l"(d) : "l"(a));
}
__device__ __forceinline__ float ex2(float x) {
    float r; asm("ex2.approx.ftz.f32 %0, %1;" : "=f"(r) : "f"(x)); return r;
}
__device__ __forceinline__ uint32_t smem_u32(const void* p) {
    uint32_t a;
    asm("{ .reg .u64 t; cvta.to.shared.u64 t, %1; cvt.u32.u64 %0, t; }"
        : "=r"(a) : "l"(p));
    return a;
}
__device__ __forceinline__ void cpa16(uint32_t dst, const void* src) {
    asm volatile("cp.async.ca.shared.global [%0], [%1], 16;"
                 :: "r"(dst), "l"(src) : "memory");
}
#define CPA_COMMIT() asm volatile("cp.async.commit_group;" ::: "memory")
#define CPA_WAIT0()  asm volatile("cp.async.wait_group 0;" ::: "memory")
#define CPA_WAIT1()  asm volatile("cp.async.wait_group 1;" ::: "memory")

// ---------------------------------------------------------------------------
// GroupNorm stats -> per-channel affine coefficients
// ---------------------------------------------------------------------------
__global__ __launch_bounds__(256) void gnstat_kernel(
    const float* __restrict__ x, const float* __restrict__ gamma,
    const float* __restrict__ beta) {
    int bg = blockIdx.x;
    int b = bg >> 5, g = bg & 31;
    const float4* x4 = (const float4*)(x + ((size_t)b * C_ + g * 8) * S_);
    int tid = threadIdx.x;
    float s0 = 0.f, s1 = 0.f;
    #pragma unroll
    for (int i = tid; i < 2048; i += 256) {
        float4 v = x4[i];
        s0 += v.x + v.y + v.z + v.w;
        s1 += v.x * v.x + v.y * v.y + v.z * v.z + v.w * v.w;
    }
    __shared__ float r0[256], r1[256];
    r0[tid] = s0; r1[tid] = s1;
    __syncthreads();
    for (int s = 128; s > 0; s >>= 1) {
        if (tid < s) { r0[tid] += r0[tid + s]; r1[tid] += r1[tid + s]; }
        __syncthreads();
    }
    if (tid < 8) {
        float m = r0[0] * (1.f / 8192.f);
        float var = r1[0] * (1.f / 8192.f) - m * m;
        float inv = rsqrtf(var + EPS_);
        int c = g * 8 + tid;
        float ga = gamma[c] * inv;
        g_coefA[b * C_ + c] = ga;
        g_coefB[b * C_ + c] = beta[c] - m * ga;
    }
}

// ---------------------------------------------------------------------------
// Merged prep kernel (validated round 12).
// ---------------------------------------------------------------------------
__global__ __launch_bounds__(256) void prep_all(
    const float* __restrict__ wq, const float* __restrict__ wp) {
    __shared__ float T[32][36];
    int bid = blockIdx.x;
    int tid = threadIdx.x;
    if (bid < 768) {
        int b = bid / 192, t = bid % 192;
        int kt = t / 24, mt = t % 24;
        int m0 = mt * 32, k0 = kt * 32;
        int r = tid >> 3, c4 = (tid & 7) * 4;
        *(float4*)&T[r][c4] = *(const float4*)&wq[(size_t)(m0 + r) * C_ + k0 + c4];
        __syncthreads();
        int kk = r, m4 = c4;
        float a = g_coefA[b * C_ + k0 + kk];
        float4 o = make_float4(T[m4][kk] * a, T[m4 + 1][kk] * a,
                               T[m4 + 2][kk] * a, T[m4 + 3][kk] * a);
        *(float4*)&g_w4t[((size_t)b * C_ + k0 + kk) * (3 * C_) + m0 + m4] = o;
    } else if (bid < 1152) {
        int t = bid - 768;
        int b = t / 96, mg = t % 96;
        int m = mg * 8 + (tid >> 5);
        int lane = tid & 31;
        const float* cB = g_coefB + b * C_;
        float s = 0.f;
        #pragma unroll
        for (int k = lane; k < C_; k += 32) s += wq[(size_t)m * C_ + k] * cB[k];
        #pragma unroll
        for (int msk = 16; msk > 0; msk >>= 1)
            s += __shfl_xor_sync(0xffffffffu, s, msk);
        if (lane == 0) g_bias4[b * 3 * C_ + m] = s;
    } else {
        int t = bid - 1152;
        int mt = t % 8, kt = t / 8;
        int m0 = mt * 32, k0 = kt * 32;
        int r = tid >> 3, c4 = (tid & 7) * 4;
        *(float4*)&T[r][c4] = *(const float4*)&wp[(size_t)(m0 + r) * C_ + k0 + c4];
        __syncthreads();
        int kk = r, m4 = c4;
        float4 o = make_float4(T[m4][kk], T[m4 + 1][kk], T[m4 + 2][kk], T[m4 + 3][kk]);
        *(float4*)&g_wprojT[(size_t)(k0 + kk) * C_ + m0 + m4] = o;
    }
}

// ---------------------------------------------------------------------------
// cp.async pipelined GEMM (validated rounds 11/12).
// ---------------------------------------------------------------------------
template <bool QKV, int BM, int RM>
__global__ __launch_bounds__(256, 3) void gemm_cp(
    const float* __restrict__ WT, const float* __restrict__ X,
    float* __restrict__ Out, const float* __restrict__ bias,
    const float* __restrict__ resid, int M) {
    __shared__ __align__(16) float As[2][16][BM];
    __shared__ __align__(16) float Bs[2][16][64];
    const int NA = BM / 64;

    int tid = threadIdx.x;
    int b = blockIdx.z, m0 = blockIdx.y * BM, n0 = blockIdx.x * 64;
    const float* Wb = WT + (QKV ? (size_t)b * C_ * M : 0);
    const float* Xb = X + (size_t)b * C_ * S_;
    uint32_t aA[2] = { smem_u32(&As[0][0][0]), smem_u32(&As[1][0][0]) };
    uint32_t aB[2] = { smem_u32(&Bs[0][0][0]), smem_u32(&Bs[1][0][0]) };

#define LOADST(CH, ST) do {                                                   \
    int kb_ = (CH) * 16;                                                      \
    _Pragma("unroll")                                                         \
    for (int u_ = 0; u_ < NA; u_++) {                                         \
        int idx_ = tid + u_ * 256;                                            \
        int k_ = idx_ / (BM / 4), m4_ = (idx_ % (BM / 4)) * 4;                \
        cpa16(aA[ST] + (k_ * BM + m4_) * 4,                                   \
              Wb + (size_t)(kb_ + k_) * M + m0 + m4_);                        \
    }                                                                         \
    {                                                                         \
        int k_ = tid >> 4, n4_ = (tid & 15) * 4;                              \
        cpa16(aB[ST] + (k_ * 64 + n4_) * 4,                                   \
              Xb + (size_t)(kb_ + k_) * S_ + n0 + n4_);                       \
    }                                                                         \
} while (0)

    LOADST(0, 0); CPA_COMMIT();
    LOADST(1, 1); CPA_COMMIT();

    int rg = tid >> 4, cg = tid & 15;
    u64 acc[RM][2] = {};

    #pragma unroll
    for (int ch = 0; ch < 16; ch++) {
        int st = ch & 1;
        if (ch == 15) { CPA_WAIT0(); } else { CPA_WAIT1(); }
        __syncthreads();
        #pragma unroll
        for (int k = 0; k < 16; k++) {
            float4 bv = *(float4*)&Bs[st][k][cg * 4];
            u64 bp0 = pk2(bv.x, bv.y), bp1 = pk2(bv.z, bv.w);
            float a[RM];
            #pragma unroll
            for (int t = 0; t < RM / 4; t++) {
                float4 av = *(float4*)&As[st][k][rg * RM + t * 4];
                a[t * 4 + 0] = av.x; a[t * 4 + 1] = av.y;
                a[t * 4 + 2] = av.z; a[t * 4 + 3] = av.w;
            }
            #pragma unroll
            for (int i = 0; i < RM; i++) {
                u64 ab = pk2(a[i], a[i]);
                fma2(acc[i][0], ab, bp0);
                fma2(acc[i][1], ab, bp1);
            }
        }
        __syncthreads();
        if (ch + 2 < 16) { LOADST(ch + 2, st); CPA_COMMIT(); }
    }
#undef LOADST

    float o[RM][4];
    #pragma unroll
    for (int i = 0; i < RM; i++) {
        upk2(o[i][0], o[i][1], acc[i][0]);
        upk2(o[i][2], o[i][3], acc[i][1]);
    }

    if (QKV && m0 >= 512) {
        #pragma unroll
        for (int i = 0; i < RM; i++) {
            float bv = bias[b * M + m0 + rg * RM + i];
            #pragma unroll
            for (int u = 0; u < 4; u++) o[i][u] += bv;
        }
        int mb = m0 - 512 + rg * RM;
        int h = mb >> 5, db = mb & 31;
        float* vdst = g_vt + (size_t)(b * 8 + h) * 1024 * 32;
        #pragma unroll
        for (int u = 0; u < 4; u++) {
            int s = n0 + cg * 4 + u;
            *(float4*)&vdst[(size_t)s * 32 + db] =
                make_float4(o[0][u], o[1][u], o[2][u], o[3][u]);
            *(float4*)&vdst[(size_t)s * 32 + db + 4] =
                make_float4(o[4][u], o[5][u], o[6][u], o[7][u]);
        }
        return;
    }

    #pragma unroll
    for (int i = 0; i < RM; i++) {
        int m = m0 + rg * RM + i;
        float bv = bias[(QKV ? b * M : 0) + m];
        size_t off = ((size_t)b * M + m) * S_ + n0 + cg * 4;
        float4 v = make_float4(o[i][0] + bv, o[i][1] + bv,
                               o[i][2] + bv, o[i][3] + bv);
        if (!QKV) {
            float4 rr = *(const float4*)&resid[off];
            v.x += rr.x; v.y += rr.y; v.z += rr.z; v.w += rr.w;
        }
        *(float4*)&Out[off] = v;
    }
}

// ---------------------------------------------------------------------------
// Fused flash attention (BQ=128) with j-pair K loads:
// thread owns j = 2cg + 32jj + {0,1}; K loaded as LDS.64 pairs that feed
// fma2 directly (no K packing MOVs). P store/PV/epilogue structure unchanged.
// ---------------------------------------------------------------------------
#define FL_QS   0
#define FL_KS0  4224
#define FL_KS1  8448
#define FL_VT0  12672
#define FL_VT1  17280
#define FL_PS   21888
#define FL_MX   38784
#define FL_SL   38912
#define FL_SC   39040
#define FL_TOT  39168
#define RED_STR 36
#define RED_SZ  (128 * RED_STR)

__global__ __launch_bounds__(256) void flash_kernel() {
    extern __shared__ float sh[];
    float* Qs  = sh + FL_QS;
    float* Ps  = sh + FL_PS;
    float* smx = sh + FL_MX;
    float* sl  = sh + FL_SL;
    float* sc  = sh + FL_SC;

    int tid = threadIdx.x;
    int bh = blockIdx.y, b = bh >> 3, h = bh & 7;
    int i0 = blockIdx.x * 128;
    const float* qb  = g_qkv + ((size_t)(b * 768 + h * 32)) * 1024;
    const float* kb  = g_qkv + ((size_t)(b * 768 + 256 + h * 32)) * 1024;
    const float* vtg = g_vt + (size_t)bh * 1024 * 32;

    uint32_t ksb[2] = { smem_u32(sh + FL_KS0), smem_u32(sh + FL_KS1) };
    uint32_t vtb[2] = { smem_u32(sh + FL_VT0), smem_u32(sh + FL_VT1) };

    #pragma unroll
    for (int t = 0; t < 4; t++) {
        int idx = tid + t * 256;
        int d = idx >> 5, c4 = (idx & 31) * 4;
        cpa16(ksb[0] + (d * 132 + c4) * 4, kb + (size_t)d * 1024 + c4);
        int j = idx >> 3, d4 = (idx & 7) * 4;
        cpa16(vtb[0] + (j * 36 + d4) * 4, vtg + (size_t)j * 32 + d4);
    }
    CPA_COMMIT();

    #pragma unroll
    for (int t = 0; t < 4; t++) {
        int idx = tid + t * 256;
        int d = idx >> 5, c4 = (idx & 31) * 4;
        *(float4*)&Qs[d * 132 + c4] = *(const float4*)(qb + (size_t)d * 1024 + i0 + c4);
    }
    if (tid < 128) { smx[tid] = -1e30f; sl[tid] = 0.f; }

    const int rg = tid >> 4, cg = tid & 15, ri0 = rg * 8;
    const int jgrp = tid >> 6, r6 = tid & 63;
    const int i8 = (r6 >> 2) * 8, d0 = (r6 & 3) * 8;

    u64 Oa[8][4] = {};

    for (int jt = 0; jt < 8; jt++) {
        float* Ks = sh + ((jt & 1) ? FL_KS1 : FL_KS0);
        float* Vt = sh + ((jt & 1) ? FL_VT1 : FL_VT0);
        CPA_WAIT0();
        __syncthreads();
        if (jt < 7) {
            int j1 = (jt + 1) * 128;
            int bn = (jt + 1) & 1;
            #pragma unroll
            for (int t = 0; t < 4; t++) {
                int idx = tid + t * 256;
                int d = idx >> 5, c4 = (idx & 31) * 4;
                cpa16(ksb[bn] + (d * 132 + c4) * 4, kb + (size_t)d * 1024 + j1 + c4);
                int j = idx >> 3, d4 = (idx & 7) * 4;
                cpa16(vtb[bn] + (j * 36 + d4) * 4, vtg + (size_t)(j1 + j) * 32 + d4);
            }
            CPA_COMMIT();
        }

        // --- QK^T: 8i x (4 j-pairs). K pair loaded as LDS.64 -> direct fma2.
        u64 qk[8][4] = {};
        #pragma unroll
        for (int d = 0; d < 32; d++) {
            float4 q0 = *(float4*)&Qs[d * 132 + ri0];
            float4 q1 = *(float4*)&Qs[d * 132 + ri0 + 4];
            u64 qd[8] = { pk2(q0.x, q0.x), pk2(q0.y, q0.y),
                          pk2(q0.z, q0.z), pk2(q0.w, q0.w),
                          pk2(q1.x, q1.x), pk2(q1.y, q1.y),
                          pk2(q1.z, q1.z), pk2(q1.w, q1.w) };
            u64 kp[4];
            #pragma unroll
            for (int jj = 0; jj < 4; jj++)
                kp[jj] = *(const u64*)&Ks[d * 132 + 2 * cg + 32 * jj];
            #pragma unroll
            for (int ii = 0; ii < 8; ii++) {
                fma2(qk[ii][0], qd[ii], kp[0]);
                fma2(qk[ii][1], qd[ii], kp[1]);
                fma2(qk[ii][2], qd[ii], kp[2]);
                fma2(qk[ii][3], qd[ii], kp[3]);
            }
        }
        // s[ii][2jj+e] = P(i, 2cg + 32jj + e)
        float s[8][8];
        #pragma unroll
        for (int ii = 0; ii < 8; ii++)
            #pragma unroll
            for (int jj = 0; jj < 4; jj++)
                upk2(s[ii][2 * jj], s[ii][2 * jj + 1], qk[ii][jj]);

        // --- online softmax (8 rows/thread, reduce over 16 cg lanes) ---
        float mold[8], mnew[8], rsum[8];
        #pragma unroll
        for (int ii = 0; ii < 8; ii++) {
            float mx = s[ii][0];
            #pragma unroll
            for (int jj = 1; jj < 8; jj++) mx = fmaxf(mx, s[ii][jj]);
            #pragma unroll
            for (int msk = 1; msk < 16; msk <<= 1)
                mx = fmaxf(mx, __shfl_xor_sync(0xffffffffu, mx, msk));
            mold[ii] = smx[ri0 + ii];
            mnew[ii] = fmaxf(mold[ii], mx);
            float nk = -mnew[ii] * KK2;
            float r = 0.f;
            #pragma unroll
            for (int jj = 0; jj < 8; jj++) {
                float p = ex2(fmaf(s[ii][jj], KK2, nk));
                s[ii][jj] = p;
                r += p;
            }
            #pragma unroll
            for (int msk = 1; msk < 16; msk <<= 1)
                r += __shfl_xor_sync(0xffffffffu, r, msk);
            rsum[ii] = r;
        }
        if (cg == 0) {
            #pragma unroll
            for (int ii = 0; ii < 8; ii++) {
                float c = ex2((mold[ii] - mnew[ii]) * KK2);
                sc[ri0 + ii] = c;
                smx[ri0 + ii] = mnew[ii];
                sl[ri0 + ii] = sl[ri0 + ii] * c + rsum[ii];
            }
        }
        // store P j-major: col = 2cg + 32jj + e
        #pragma unroll
        for (int c8 = 0; c8 < 8; c8++) {
            int col = 2 * cg + 32 * (c8 >> 1) + (c8 & 1);
            *(float4*)&Ps[col * 132 + ri0] =
                make_float4(s[0][c8], s[1][c8], s[2][c8], s[3][c8]);
            *(float4*)&Ps[col * 132 + ri0 + 4] =
                make_float4(s[4][c8], s[5][c8], s[6][c8], s[7][c8]);
        }
        __syncthreads();

        // --- P @ V: 8i x 8d over this thread's 32-j quarter ---
        #pragma unroll
        for (int ii = 0; ii < 8; ii++) {
            float cc = sc[i8 + ii];
            u64 cb = pk2(cc, cc);
            mul2(Oa[ii][0], cb); mul2(Oa[ii][1], cb);
            mul2(Oa[ii][2], cb); mul2(Oa[ii][3], cb);
        }
        int jb = jgrp * 32;
        #pragma unroll 2
        for (int jo = 0; jo < 32; jo++) {
            int j = jb + jo;
            float4 p0 = *(float4*)&Ps[j * 132 + i8];
            float4 p1 = *(float4*)&Ps[j * 132 + i8 + 4];
            float pv[8] = { p0.x, p0.y, p0.z, p0.w, p1.x, p1.y, p1.z, p1.w };
            float4 v0 = *(float4*)&Vt[j * 36 + d0];
            float4 v1 = *(float4*)&Vt[j * 36 + d0 + 4];
            u64 vp[4] = { pk2(v0.x, v0.y), pk2(v0.z, v0.w),
                          pk2(v1.x, v1.y), pk2(v1.z, v1.w) };
            #pragma unroll
            for (int ii = 0; ii < 8; ii++) {
                u64 pbx = pk2(pv[ii], pv[ii]);
                fma2(Oa[ii][0], pbx, vp[0]);
                fma2(Oa[ii][1], pbx, vp[1]);
                fma2(Oa[ii][2], pbx, vp[2]);
                fma2(Oa[ii][3], pbx, vp[3]);
            }
        }
    }
    __syncthreads();

    // 4-way partial reduce via Ps scratch (stride 36, 16B aligned)
    float o[8][8];
    #pragma unroll
    for (int ii = 0; ii < 8; ii++) {
        upk2(o[ii][0], o[ii][1], Oa[ii][0]);
        upk2(o[ii][2], o[ii][3], Oa[ii][1]);
        upk2(o[ii][4], o[ii][5], Oa[ii][2]);
        upk2(o[ii][6], o[ii][7], Oa[ii][3]);
    }
    if (jgrp > 0) {
        float* dst = Ps + (jgrp - 1) * RED_SZ;
        #pragma unroll
        for (int ii = 0; ii < 8; ii++) {
            *(float4*)&dst[(i8 + ii) * RED_STR + d0] =
                make_float4(o[ii][0], o[ii][1], o[ii][2], o[ii][3]);
            *(float4*)&dst[(i8 + ii) * RED_STR + d0 + 4] =
                make_float4(o[ii][4], o[ii][5], o[ii][6], o[ii][7]);
        }
    }
    __syncthreads();
    if (jgrp == 0) {
        float* ob = g_att + ((size_t)(b * 256 + h * 32)) * 1024 + i0;
        #pragma unroll
        for (int ii = 0; ii < 8; ii++) {
            #pragma unroll
            for (int g = 0; g < 3; g++) {
                float4 pa = *(float4*)&Ps[g * RED_SZ + (i8 + ii) * RED_STR + d0];
                float4 pb2 = *(float4*)&Ps[g * RED_SZ + (i8 + ii) * RED_STR + d0 + 4];
                o[ii][0] += pa.x;  o[ii][1] += pa.y;
                o[ii][2] += pa.z;  o[ii][3] += pa.w;
                o[ii][4] += pb2.x; o[ii][5] += pb2.y;
                o[ii][6] += pb2.z; o[ii][7] += pb2.w;
            }
            float linv = 1.f / sl[i8 + ii];
            #pragma unroll
            for (int dd = 0; dd < 8; dd++) o[ii][dd] *= linv;
        }
        #pragma unroll
        for (int dd = 0; dd < 8; dd++) {
            *(float4*)&ob[(size_t)(d0 + dd) * 1024 + i8] =
                make_float4(o[0][dd], o[1][dd], o[2][dd], o[3][dd]);
            *(float4*)&ob[(size_t)(d0 + dd) * 1024 + i8 + 4] =
                make_float4(o[4][dd], o[5][dd], o[6][dd], o[7][dd]);
        }
    }
}

// ---------------------------------------------------------------------------
extern "C" void kernel_launch(void* const* d_in, const int* in_sizes, int n_in,
                              void* d_out, int out_size) {
    const float* x      = (const float*)d_in[0];
    const float* gamma  = (const float*)d_in[1];
    const float* beta   = (const float*)d_in[2];
    const float* w_qkv  = (const float*)d_in[3];
    const float* w_proj = (const float*)d_in[4];
    const float* b_proj = (const float*)d_in[5];
    float* out = (float*)d_out;

    float* qkv;   cudaGetSymbolAddress((void**)&qkv, g_qkv);
    float* att;   cudaGetSymbolAddress((void**)&att, g_att);
    float* w4t;   cudaGetSymbolAddress((void**)&w4t, g_w4t);
    float* bias4; cudaGetSymbolAddress((void**)&bias4, g_bias4);
    float* wpT;   cudaGetSymbolAddress((void**)&wpT, g_wprojT);

    static int smem_set = 0;
    const int FLASH_SMEM = FL_TOT * 4;
    if (!smem_set) {
        cudaFuncSetAttribute(flash_kernel,
                             cudaFuncAttributeMaxDynamicSharedMemorySize,
                             FLASH_SMEM);
        smem_set = 1;
    }

    // 1. GroupNorm stats
    gnstat_kernel<<<B_ * 32, 256>>>(x, gamma, beta);

    // 2. Merged weight preps
    prep_all<<<1216, 256>>>(w_qkv, w_proj);

    // 3. QKV GEMM (V -> g_vt transposed)
    {
        dim3 grid(S_ / 64, (3 * C_) / 128, B_);
        gemm_cp<true, 128, 8><<<grid, 256>>>(w4t, x, qkv, bias4, nullptr, 3 * C_);
    }

    // 4. Fused flash attention (BQ=128, j-pair K loads)
    {
        dim3 grid(S_ / 128, B_ * HEADS_);
        flash_kernel<<<grid, 256, FLASH_SMEM>>>();
    }

    // 5. Proj + bias + residual
    {
        dim3 grid(S_ / 64, C_ / 64, B_);
        gemm_cp<false, 64, 4><<<grid, 256>>>(wpT, att, out, b_proj, x, C_);
    }
}